// round 8
// baseline (speedup 1.0000x reference)
#include <cuda_runtime.h>
#include <cuda_bf16.h>
#include <math.h>
#include <stdint.h>

#define TOKENS 16384
#define DDIM   2048
#define NEXP   64
#define HDIM   1024

// Output layout (float32): idx [16384*2] | scores [16384*2] | probs [16384*64] | imp [64] | load [64]
#define OFF_IDX   0
#define OFF_SC    32768
#define OFF_P     65536
#define OFF_IMP   1114112
#define OFF_LOAD  1114176

// ---------------- scratch ----------------
__device__ __nv_bfloat16 g_w1[(size_t)HDIM * DDIM];
__device__ __nv_bfloat16 g_wg_hi[(size_t)NEXP * DDIM];
__device__ __nv_bfloat16 g_wg_lo[(size_t)NEXP * DDIM];
__device__ float g_logits[(size_t)TOKENS * NEXP];
__device__ float g_diffpre[TOKENS];
__device__ float g_mu[TOKENS];
__device__ float g_rstd[TOKENS];
__device__ float g_c1[HDIM];
__device__ float g_c2[HDIM];
__device__ float g_imp[NEXP];
__device__ int   g_loadcnt[NEXP];

// =========================================================================
// prep: W1/Wg conversion + zero + LN stats + C1/C2 vectors, one launch.
// grid = 8192 (convert) + 2048 (stats, 8 tok/blk) + 128 (C1/C2, 8 n/blk)
// =========================================================================
__global__ __launch_bounds__(256)
void prep_kernel(const float* __restrict__ W1, const float* __restrict__ Wg,
                 const float* __restrict__ x, const float* __restrict__ gamma,
                 const float* __restrict__ beta) {
    int b = blockIdx.x;
    int tid = threadIdx.x;
    if (b < 8192) {
        int i = b * 256 + tid;
        g_w1[i] = __float2bfloat16(W1[i]);
        if (i < NEXP * DDIM) {
            float v = Wg[i];
            __nv_bfloat16 hi = __float2bfloat16(v);
            g_wg_hi[i] = hi;
            g_wg_lo[i] = __float2bfloat16(v - __bfloat162float(hi));
        }
        if (i < TOKENS) g_diffpre[i] = 0.f;
        if (i < NEXP) { g_loadcnt[i] = 0; g_imp[i] = 0.f; }
    } else if (b < 10240) {
        int t = (b - 8192) * 8 + (tid >> 5);
        int lane = tid & 31;
        const float4* xr = (const float4*)(x + (size_t)t * DDIM);
        float s = 0.f, q = 0.f;
        #pragma unroll
        for (int k = 0; k < 16; k++) {
            float4 v = xr[lane + k * 32];
            s += v.x + v.y + v.z + v.w;
            q += v.x*v.x + v.y*v.y + v.z*v.z + v.w*v.w;
        }
        #pragma unroll
        for (int off = 16; off; off >>= 1) {
            s += __shfl_xor_sync(0xffffffffu, s, off);
            q += __shfl_xor_sync(0xffffffffu, q, off);
        }
        if (lane == 0) {
            float mean = s * (1.f / DDIM);
            float var  = q * (1.f / DDIM) - mean * mean;
            g_mu[t]   = mean;
            g_rstd[t] = rsqrtf(var + 1e-5f);
        }
    } else {
        int n = (b - 10240) * 8 + (tid >> 5);
        int lane = tid & 31;
        const float* wr = W1 + (size_t)n * DDIM;
        float c1 = 0.f, c2 = 0.f;
        #pragma unroll 8
        for (int k = 0; k < 64; k++) {
            int d = lane + k * 32;
            float w = wr[d];
            c1 += w * gamma[d];
            c2 += w * beta[d];
        }
        #pragma unroll
        for (int off = 16; off; off >>= 1) {
            c1 += __shfl_xor_sync(0xffffffffu, c1, off);
            c2 += __shfl_xor_sync(0xffffffffu, c2, off);
        }
        if (lane == 0) { g_c1[n] = c1; g_c2[n] = c2; }
    }
}

// =========================================================================
// merged GEMM: grid (5, 128). bn<4: W1 path (A = bf16(x*gamma), BN=256,
// affine+GELU*W2 epilogue). bn==4: base-logits path (bf16x3 split, N=64).
// Shared skeleton: 3-stage cp.async B-ring, double-buffered A built from x.
// =========================================================================
#define MG_STAGES 3
#define MG_BK     32
#define MG_STG    16384
#define MG_A_OFF  (MG_STAGES * MG_STG)       // 49152 (A hi, 2 x 8KB)
#define MG_ALO_OFF (MG_A_OFF + 16384)        // 65536 (A lo, 2 x 8KB; logits only)
#define MG_G_OFF  (MG_ALO_OFF + 16384)       // 81920 (gamma, 8KB; W1 only)
#define MG_SMEM   (MG_G_OFF + 8192)          // 90112
#define MG_CHUNKS (DDIM / MG_BK)

__device__ __forceinline__ uint32_t smem_u32(const void* p) {
    uint32_t a;
    asm("{ .reg .u64 t; cvta.to.shared.u64 t, %1; cvt.u32.u64 %0, t; }" : "=r"(a) : "l"(p));
    return a;
}
__device__ __forceinline__ uint32_t g1_sw(uint32_t r, uint32_t c) {
    return r * 64 + ((c ^ ((r >> 1) & 3)) * 16);
}
__device__ __forceinline__ void ldsm_x4(uint32_t& r0, uint32_t& r1, uint32_t& r2, uint32_t& r3,
                                        uint32_t addr) {
    asm volatile("ldmatrix.sync.aligned.m8n8.x4.shared.b16 {%0,%1,%2,%3}, [%4];"
                 : "=r"(r0), "=r"(r1), "=r"(r2), "=r"(r3) : "r"(addr));
}
__device__ __forceinline__ float gelu_exact(float v) {
    return 0.5f * v * (1.0f + erff(v * 0.70710678118654752440f));
}
#define MMA_BF16(acc, a, b0, b1) \
    asm volatile( \
        "mma.sync.aligned.m16n8k16.row.col.f32.bf16.bf16.f32 " \
        "{%0,%1,%2,%3}, {%4,%5,%6,%7}, {%8,%9}, {%0,%1,%2,%3};\n" \
        : "+f"((acc)[0]), "+f"((acc)[1]), "+f"((acc)[2]), "+f"((acc)[3]) \
        : "r"((a)[0]), "r"((a)[1]), "r"((a)[2]), "r"((a)[3]), "r"(b0), "r"(b1))

__global__ __launch_bounds__(256, 1)
void merged_gemm(const float* __restrict__ x, const float* __restrict__ gamma,
                 const float* __restrict__ W2) {
    extern __shared__ __align__(128) char msm[];
    uint32_t sb = smem_u32(msm);
    int tid = threadIdx.x;
    int warp = tid >> 5, lane = tid & 31;
    int bn = blockIdx.x, bm = blockIdx.y;

    const float* xb = x + (size_t)(bm * 128) * DDIM;
    int r0 = tid >> 1;
    int hsel = tid & 1;
    int lrow = lane & 15;
    int lsel = lane >> 4;

    if (bn < 4) {
        // ================= W1 path =================
        int wm = (warp & 1) * 64;
        int wn = (warp >> 1) * 64;
        const __nv_bfloat16* Bg = g_w1 + (size_t)(bn * 256) * DDIM;

        float* sG = (float*)(msm + MG_G_OFF);
        #pragma unroll
        for (int i = 0; i < 2; i++) {
            int idx = tid + i * 256;
            ((float4*)sG)[idx] = ((const float4*)gamma)[idx];
        }

        float acc[4][8][4];
        #pragma unroll
        for (int i = 0; i < 4; i++)
            #pragma unroll
            for (int j = 0; j < 8; j++)
                #pragma unroll
                for (int r = 0; r < 4; r++) acc[i][j][r] = 0.f;

        // B prologue
        #pragma unroll
        for (int st = 0; st < 2; st++) {
            #pragma unroll
            for (int i = 0; i < 4; i++) {
                int idx = tid + i * 256;
                int r = idx >> 2, c = idx & 3;
                uint32_t dst = sb + st * MG_STG + g1_sw(r, c);
                asm volatile("cp.async.cg.shared.global [%0], [%1], 16;\n"
                             :: "r"(dst), "l"(Bg + (size_t)r * DDIM + st * MG_BK + c * 8));
            }
            asm volatile("cp.async.commit_group;\n");
        }
        float4 xv[4];
        #pragma unroll
        for (int i = 0; i < 4; i++)
            xv[i] = *(const float4*)&xb[(size_t)r0 * DDIM + hsel * 16 + i * 4];
        __syncthreads();

        #pragma unroll 1
        for (int c = 0; c < MG_CHUNKS; c++) {
            if (c + 2 < MG_CHUNKS) {
                int k0 = (c + 2) * MG_BK;
                uint32_t base = sb + ((c + 2) % MG_STAGES) * MG_STG;
                #pragma unroll
                for (int i = 0; i < 4; i++) {
                    int idx = tid + i * 256;
                    int r = idx >> 2, cc = idx & 3;
                    uint32_t dst = base + g1_sw(r, cc);
                    asm volatile("cp.async.cg.shared.global [%0], [%1], 16;\n"
                                 :: "r"(dst), "l"(Bg + (size_t)r * DDIM + k0 + cc * 8));
                }
                asm volatile("cp.async.commit_group;\n");
            }
            {
                const float* gg = sG + c * 32 + hsel * 16;
                uint32_t sA = sb + MG_A_OFF + (c & 1) * 8192;
                __align__(16) __nv_bfloat16 ob[16];
                #pragma unroll
                for (int i = 0; i < 4; i++) {
                    float4 t4 = xv[i];
                    float4 g4 = *(const float4*)(gg + i * 4);
                    ob[i*4+0] = __float2bfloat16(t4.x * g4.x);
                    ob[i*4+1] = __float2bfloat16(t4.y * g4.y);
                    ob[i*4+2] = __float2bfloat16(t4.z * g4.z);
                    ob[i*4+3] = __float2bfloat16(t4.w * g4.w);
                }
                #pragma unroll
                for (int j = 0; j < 2; j++) {
                    uint32_t dst = sA + g1_sw((uint32_t)r0, (uint32_t)(hsel * 2 + j));
                    *(uint4*)(msm + (dst - sb)) = *(uint4*)&ob[j * 8];
                }
            }
            if (c + 1 < MG_CHUNKS) {
                #pragma unroll
                for (int i = 0; i < 4; i++)
                    xv[i] = *(const float4*)&xb[(size_t)r0 * DDIM + (c + 1) * MG_BK + hsel * 16 + i * 4];
            }
            if (c + 2 < MG_CHUNKS) {
                asm volatile("cp.async.wait_group 2;\n");
            } else if (c + 2 == MG_CHUNKS) {
                asm volatile("cp.async.wait_group 1;\n");
            } else {
                asm volatile("cp.async.wait_group 0;\n");
            }
            __syncthreads();

            uint32_t sA = sb + MG_A_OFF + (c & 1) * 8192;
            uint32_t sB = sb + (c % MG_STAGES) * MG_STG;
            #pragma unroll
            for (int ks = 0; ks < 2; ks++) {
                uint32_t af[4][4], bf[8][2];
                #pragma unroll
                for (int i = 0; i < 4; i++) {
                    uint32_t r = (uint32_t)(wm + i * 16 + lrow);
                    ldsm_x4(af[i][0], af[i][1], af[i][2], af[i][3],
                            sA + g1_sw(r, (uint32_t)(ks * 2 + lsel)));
                }
                #pragma unroll
                for (int jb = 0; jb < 4; jb++) {
                    uint32_t r = (uint32_t)(wn + jb * 16 + lrow);
                    uint32_t q0, q1, q2, q3;
                    ldsm_x4(q0, q1, q2, q3, sB + g1_sw(r, (uint32_t)(ks * 2 + lsel)));
                    bf[jb * 2][0] = q0;     bf[jb * 2][1] = q2;
                    bf[jb * 2 + 1][0] = q1; bf[jb * 2 + 1][1] = q3;
                }
                #pragma unroll
                for (int i = 0; i < 4; i++)
                    #pragma unroll
                    for (int j = 0; j < 8; j++)
                        MMA_BF16(acc[i][j], af[i], bf[j][0], bf[j][1]);
            }
            __syncthreads();
        }

        // epilogue: h1 = rs*acc - rs*mu*C1[n] + C2[n]; gelu*W2; reduce
        float part0[4] = {0.f, 0.f, 0.f, 0.f};
        float part1[4] = {0.f, 0.f, 0.f, 0.f};
        float rs0[4], rm0[4], rs1[4], rm1[4];
        #pragma unroll
        for (int i = 0; i < 4; i++) {
            int m0 = bm * 128 + wm + i * 16 + (lane >> 2);
            rs0[i] = g_rstd[m0];     rm0[i] = rs0[i] * g_mu[m0];
            rs1[i] = g_rstd[m0 + 8]; rm1[i] = rs1[i] * g_mu[m0 + 8];
        }
        #pragma unroll
        for (int j = 0; j < 8; j++) {
            int n = bn * 256 + wn + j * 8 + (lane & 3) * 2;
            float2 c1 = *(const float2*)&g_c1[n];
            float2 c2 = *(const float2*)&g_c2[n];
            float2 w2 = *(const float2*)&W2[n];
            #pragma unroll
            for (int i = 0; i < 4; i++) {
                float h00 = rs0[i] * acc[i][j][0] - rm0[i] * c1.x + c2.x;
                float h01 = rs0[i] * acc[i][j][1] - rm0[i] * c1.y + c2.y;
                float h10 = rs1[i] * acc[i][j][2] - rm1[i] * c1.x + c2.x;
                float h11 = rs1[i] * acc[i][j][3] - rm1[i] * c1.y + c2.y;
                part0[i] += gelu_exact(h00) * w2.x + gelu_exact(h01) * w2.y;
                part1[i] += gelu_exact(h10) * w2.x + gelu_exact(h11) * w2.y;
            }
        }
        #pragma unroll
        for (int i = 0; i < 4; i++) {
            part0[i] += __shfl_xor_sync(0xffffffffu, part0[i], 1);
            part0[i] += __shfl_xor_sync(0xffffffffu, part0[i], 2);
            part1[i] += __shfl_xor_sync(0xffffffffu, part1[i], 1);
            part1[i] += __shfl_xor_sync(0xffffffffu, part1[i], 2);
        }
        if ((lane & 3) == 0) {
            int mbase = bm * 128 + wm + (lane >> 2);
            #pragma unroll
            for (int i = 0; i < 4; i++) {
                atomicAdd(&g_diffpre[mbase + i * 16], part0[i]);
                atomicAdd(&g_diffpre[mbase + i * 16 + 8], part1[i]);
            }
        }
    } else {
        // ================= logits path (bf16x3 split) =================
        int wm3 = (warp & 3) * 32;
        int wn3 = (warp >> 2) * 32;

        float acc[2][4][4];
        #pragma unroll
        for (int i = 0; i < 2; i++)
            #pragma unroll
            for (int j = 0; j < 4; j++)
                #pragma unroll
                for (int r = 0; r < 4; r++) acc[i][j][r] = 0.f;

        // B prologue: hi at +0, lo at +8192 within each stage
        #pragma unroll
        for (int st = 0; st < 2; st++) {
            #pragma unroll
            for (int i = 0; i < 2; i++) {
                int idx = tid + i * 256;
                int mat = idx >> 8, r = (idx >> 2) & 63, c = idx & 3;
                const __nv_bfloat16* src = (mat ? g_wg_lo : g_wg_hi)
                                         + (size_t)r * DDIM + st * MG_BK + c * 8;
                uint32_t dst = sb + st * MG_STG + mat * 8192 + g1_sw(r, c);
                asm volatile("cp.async.cg.shared.global [%0], [%1], 16;\n"
                             :: "r"(dst), "l"(src));
            }
            asm volatile("cp.async.commit_group;\n");
        }
        float4 xv[4];
        #pragma unroll
        for (int i = 0; i < 4; i++)
            xv[i] = *(const float4*)&xb[(size_t)r0 * DDIM + hsel * 16 + i * 4];
        __syncthreads();

        #pragma unroll 1
        for (int c = 0; c < MG_CHUNKS; c++) {
            if (c + 2 < MG_CHUNKS) {
                int k0 = (c + 2) * MG_BK;
                uint32_t base = sb + ((c + 2) % MG_STAGES) * MG_STG;
                #pragma unroll
                for (int i = 0; i < 2; i++) {
                    int idx = tid + i * 256;
                    int mat = idx >> 8, r = (idx >> 2) & 63, cc = idx & 3;
                    const __nv_bfloat16* src = (mat ? g_wg_lo : g_wg_hi)
                                             + (size_t)r * DDIM + k0 + cc * 8;
                    uint32_t dst = base + mat * 8192 + g1_sw(r, cc);
                    asm volatile("cp.async.cg.shared.global [%0], [%1], 16;\n"
                                 :: "r"(dst), "l"(src));
                }
                asm volatile("cp.async.commit_group;\n");
            }
            {
                uint32_t sAh = sb + MG_A_OFF + (c & 1) * 8192;
                uint32_t sAl = sb + MG_ALO_OFF + (c & 1) * 8192;
                __align__(16) __nv_bfloat16 hb[16], lb[16];
                #pragma unroll
                for (int i = 0; i < 4; i++) {
                    float vv[4] = {xv[i].x, xv[i].y, xv[i].z, xv[i].w};
                    #pragma unroll
                    for (int e = 0; e < 4; e++) {
                        __nv_bfloat16 bh = __float2bfloat16(vv[e]);
                        hb[i*4+e] = bh;
                        lb[i*4+e] = __float2bfloat16(vv[e] - __bfloat162float(bh));
                    }
                }
                #pragma unroll
                for (int j = 0; j < 2; j++) {
                    uint32_t o = g1_sw((uint32_t)r0, (uint32_t)(hsel * 2 + j));
                    *(uint4*)(msm + (sAh + o - sb)) = *(uint4*)&hb[j * 8];
                    *(uint4*)(msm + (sAl + o - sb)) = *(uint4*)&lb[j * 8];
                }
            }
            if (c + 1 < MG_CHUNKS) {
                #pragma unroll
                for (int i = 0; i < 4; i++)
                    xv[i] = *(const float4*)&xb[(size_t)r0 * DDIM + (c + 1) * MG_BK + hsel * 16 + i * 4];
            }
            if (c + 2 < MG_CHUNKS) {
                asm volatile("cp.async.wait_group 2;\n");
            } else if (c + 2 == MG_CHUNKS) {
                asm volatile("cp.async.wait_group 1;\n");
            } else {
                asm volatile("cp.async.wait_group 0;\n");
            }
            __syncthreads();

            uint32_t sAh = sb + MG_A_OFF + (c & 1) * 8192;
            uint32_t sAl = sb + MG_ALO_OFF + (c & 1) * 8192;
            uint32_t sB = sb + (c % MG_STAGES) * MG_STG;
            #pragma unroll
            for (int ks = 0; ks < 2; ks++) {
                uint32_t ah[2][4], al[2][4], bh[4][2], bl[4][2];
                #pragma unroll
                for (int i = 0; i < 2; i++) {
                    uint32_t r = (uint32_t)(wm3 + i * 16 + lrow);
                    uint32_t o = g1_sw(r, (uint32_t)(ks * 2 + lsel));
                    ldsm_x4(ah[i][0], ah[i][1], ah[i][2], ah[i][3], sAh + o);
                    ldsm_x4(al[i][0], al[i][1], al[i][2], al[i][3], sAl + o);
                }
                #pragma unroll
                for (int jb = 0; jb < 2; jb++) {
                    uint32_t r = (uint32_t)(wn3 + jb * 16 + lrow);
                    uint32_t o = g1_sw(r, (uint32_t)(ks * 2 + lsel));
                    uint32_t q0, q1, q2, q3;
                    ldsm_x4(q0, q1, q2, q3, sB + o);
                    bh[jb * 2][0] = q0;     bh[jb * 2][1] = q2;
                    bh[jb * 2 + 1][0] = q1; bh[jb * 2 + 1][1] = q3;
                    ldsm_x4(q0, q1, q2, q3, sB + 8192 + o);
                    bl[jb * 2][0] = q0;     bl[jb * 2][1] = q2;
                    bl[jb * 2 + 1][0] = q1; bl[jb * 2 + 1][1] = q3;
                }
                #pragma unroll
                for (int i = 0; i < 2; i++)
                    #pragma unroll
                    for (int j = 0; j < 4; j++) {
                        MMA_BF16(acc[i][j], ah[i], bh[j][0], bh[j][1]);
                        MMA_BF16(acc[i][j], ah[i], bl[j][0], bl[j][1]);
                        MMA_BF16(acc[i][j], al[i], bh[j][0], bh[j][1]);
                    }
            }
            __syncthreads();
        }

        #pragma unroll
        for (int i = 0; i < 2; i++)
            #pragma unroll
            for (int j = 0; j < 4; j++) {
                int row = bm * 128 + wm3 + i * 16 + (lane >> 2);
                int col = wn3 + j * 8 + (lane & 3) * 2;
                float2 c01; c01.x = acc[i][j][0]; c01.y = acc[i][j][1];
                float2 c23; c23.x = acc[i][j][2]; c23.y = acc[i][j][3];
                *(float2*)&g_logits[(size_t)row * NEXP + col] = c01;
                *(float2*)&g_logits[(size_t)(row + 8) * NEXP + col] = c23;
            }
    }
}

// ---------------- finalize: 4 tokens/warp, fused importance ----------------
__global__ __launch_bounds__(256)
void finalize_kernel(float* __restrict__ out) {
    __shared__ float simp[8 * 64];
    int warp = threadIdx.x >> 5;
    int lane = threadIdx.x & 31;
    int tbase = blockIdx.x * 32 + warp * 4;

    float2 lg[4]; float dp[4];
    #pragma unroll
    for (int tt = 0; tt < 4; tt++) {
        lg[tt] = *(const float2*)&g_logits[(size_t)(tbase + tt) * NEXP + lane * 2];
        dp[tt] = g_diffpre[tbase + tt];
    }

    float pimp0 = 0.f, pimp1 = 0.f;
    #pragma unroll
    for (int tt = 0; tt < 4; tt++) {
        int t = tbase + tt;
        float diff = 1.f / (1.f + expf(-dp[tt]));
        float denom = 1.f + diff;
        float l0 = lg[tt].x / denom;
        float l1 = lg[tt].y / denom;

        float e0 = expf(l0), e1 = expf(l1);
        float sum = e0 + e1;
        #pragma unroll
        for (int off = 16; off; off >>= 1) sum += __shfl_xor_sync(0xffffffffu, sum, off);
        float inv = 1.f / sum;
        float p0 = e0 * inv, p1 = e1 * inv;
        *(float2*)&out[OFF_P + (size_t)t * NEXP + lane * 2] = make_float2(p0, p1);
        pimp0 += p0; pimp1 += p1;

        float bv; int bi;
        if (l1 > l0) { bv = l1; bi = lane * 2 + 1; } else { bv = l0; bi = lane * 2; }
        #pragma unroll
        for (int off = 16; off; off >>= 1) {
            float ov = __shfl_xor_sync(0xffffffffu, bv, off);
            int   oi = __shfl_xor_sync(0xffffffffu, bi, off);
            if (ov > bv || (ov == bv && oi < bi)) { bv = ov; bi = oi; }
        }
        int top1 = bi;
        float c0 = (lane * 2     == top1) ? -INFINITY : l0;
        float c1 = (lane * 2 + 1 == top1) ? -INFINITY : l1;
        float bv2; int bi2;
        if (c1 > c0) { bv2 = c1; bi2 = lane * 2 + 1; } else { bv2 = c0; bi2 = lane * 2; }
        #pragma unroll
        for (int off = 16; off; off >>= 1) {
            float ov = __shfl_xor_sync(0xffffffffu, bv2, off);
            int   oi = __shfl_xor_sync(0xffffffffu, bi2, off);
            if (ov > bv2 || (ov == bv2 && oi < bi2)) { bv2 = ov; bi2 = oi; }
        }
        int top2 = bi2;

        float sel1 = (top1 & 1) ? p1 : p0;
        float pt1 = __shfl_sync(0xffffffffu, sel1, top1 >> 1);
        float sel2 = (top2 & 1) ? p1 : p0;
        float pt2 = __shfl_sync(0xffffffffu, sel2, top2 >> 1);

        float s1 = (1.0f - pt1) + pt1;
        float s2 = (1.0f - pt2) + pt2;
        float dsum = fmaxf(s1 + s2, 1e-9f);

        if (lane == 0) {
            out[OFF_IDX + t * 2]     = (float)top1;
            out[OFF_IDX + t * 2 + 1] = (float)top2;
            out[OFF_SC + t * 2]      = s1 / dsum;
            out[OFF_SC + t * 2 + 1]  = s2 / dsum;
            atomicAdd(&g_loadcnt[top1], 1);
            atomicAdd(&g_loadcnt[top2], 1);
        }
    }

    simp[warp * 64 + lane * 2]     = pimp0;
    simp[warp * 64 + lane * 2 + 1] = pimp1;
    __syncthreads();
    if (threadIdx.x < 64) {
        float a = 0.f;
        #pragma unroll
        for (int w = 0; w < 8; w++) a += simp[w * 64 + threadIdx.x];
        atomicAdd(&g_imp[threadIdx.x], a);
    }
}

// ---------------- write importance / load ----------------
__global__ void stats_out_kernel(float* __restrict__ out) {
    int e = threadIdx.x;
    out[OFF_IMP + e]  = g_imp[e] * (1.f / TOKENS);
    out[OFF_LOAD + e] = (float)g_loadcnt[e] * (1.f / TOKENS);
}

// ---------------- launch ----------------
extern "C" void kernel_launch(void* const* d_in, const int* in_sizes, int n_in,
                              void* d_out, int out_size) {
    const float* x     = (const float*)d_in[0];
    const float* Wg    = (const float*)d_in[1];
    const float* gamma = (const float*)d_in[2];
    const float* beta  = (const float*)d_in[3];
    const float* W1    = (const float*)d_in[4];
    const float* W2    = (const float*)d_in[5];
    float* out = (float*)d_out;

    cudaFuncSetAttribute(merged_gemm, cudaFuncAttributeMaxDynamicSharedMemorySize, MG_SMEM);

    prep_kernel<<<10368, 256>>>(W1, Wg, x, gamma, beta);
    dim3 g3(5, TOKENS / 128);
    merged_gemm<<<g3, 256, MG_SMEM>>>(x, gamma, W2);
    finalize_kernel<<<TOKENS / 32, 256>>>(out);
    stats_out_kernel<<<1, NEXP>>>(out);
}